// round 6
// baseline (speedup 1.0000x reference)
#include <cuda_runtime.h>
#include <cuda_fp16.h>
#include <cstdint>
#include <cstddef>

// BahdanauAttention B=16, T=8192, D=256, U=256 fp32.
// Baseline-PTX (ptxas sm_100): fp16 mma.sync + ldmatrix, persistent score kernel.
// Fused: score GEMM + tanh*V epilogue + exp + per-tile context partials (values
// read exactly ONCE from DRAM). Then tiny Z-sum, weight-normalize, partial-reduce.

#define Bn 16
#define Tn 8192
#define Dn 256
#define Un 256
#define TM 64                       // score tile M
#define TPB 128                     // tiles per batch
#define NTILES (Bn * TPB)           // 2048
#define GRID_SCORE 148

__device__ float g_escore[Bn * Tn];        // exp(score)
__device__ float g_biasq[Bn * Un];
__device__ float g_Z[Bn];
__device__ float g_zp[NTILES * 2];         // per-tile partial sums of exp
__device__ float g_partial[NTILES * Dn];   // per-tile unnormalized context partials

// ---------------- helpers ----------------

__device__ __forceinline__ float tanh_fast(float x) {
    float y;
    asm("tanh.approx.f32 %0, %1;" : "=f"(y) : "f"(x));
    return y;
}

__device__ __forceinline__ uint32_t pack_half2(float x, float y) {
    __half2 h = __floats2half2_rn(x, y);
    return *(uint32_t*)&h;
}

__device__ __forceinline__ uint32_t smem_u32(const void* p) {
    uint32_t a;
    asm("{ .reg .u64 t; cvta.to.shared.u64 t, %1; cvt.u32.u64 %0, t; }" : "=r"(a) : "l"(p));
    return a;
}

__device__ __forceinline__ void mma_fp16(float* c, const uint32_t* a, uint32_t b0, uint32_t b1) {
    asm volatile(
        "mma.sync.aligned.m16n8k16.row.col.f32.f16.f16.f32 "
        "{%0,%1,%2,%3},{%4,%5,%6,%7},{%8,%9},{%0,%1,%2,%3};"
        : "+f"(c[0]), "+f"(c[1]), "+f"(c[2]), "+f"(c[3])
        : "r"(a[0]), "r"(a[1]), "r"(a[2]), "r"(a[3]), "r"(b0), "r"(b1));
}

#define LDSM4(r, addr) \
    asm volatile("ldmatrix.sync.aligned.m8n8.x4.shared.b16 {%0,%1,%2,%3}, [%4];" \
                 : "=r"((r)[0]), "=r"((r)[1]), "=r"((r)[2]), "=r"((r)[3]) : "r"(addr))

// ---------------- smem layout (bytes) ----------------
#define SAW 132
#define ABUF_BYTES 33792                    // 64 rows x 132 words x 4B
#define SM_A 0
#define SM_B (2 * ABUF_BYTES)               // 67584
#define SM_SROW (SM_B + 135168)             // 202752
#define SM_SES (SM_SROW + 2048)             // 204800
#define SM_SPART (SM_SES + 256)             // 205056
#define SM_TOTAL (SM_SPART + 4096)          // 209152

// ---------------- kernel 0: biasq[b,u] = W1_b + W2_b + query@W2 ----------------

__global__ __launch_bounds__(256)
void projq_kernel(const float* __restrict__ query, const float* __restrict__ W2,
                  const float* __restrict__ W2b, const float* __restrict__ W1b) {
    int u = threadIdx.x, b = blockIdx.x;
    __shared__ float q[Dn];
    if (u < Dn) q[u] = query[b * Dn + u];
    __syncthreads();
    float acc[8] = {0.f, 0.f, 0.f, 0.f, 0.f, 0.f, 0.f, 0.f};
#pragma unroll 4
    for (int d0 = 0; d0 < Dn; d0 += 8) {
#pragma unroll
        for (int j = 0; j < 8; ++j)
            acc[j] += q[d0 + j] * __ldg(W2 + (size_t)(d0 + j) * Un + u);
    }
    float s = ((acc[0] + acc[1]) + (acc[2] + acc[3])) + ((acc[4] + acc[5]) + (acc[6] + acc[7]));
    g_biasq[b * Un + u] = s + W2b[u] + W1b[u];
}

// ---------------- kernel 1: persistent fused score+context kernel ----------------
// Grid 148 x 512 threads. W1 staged once. Per tile (M=64, K=256, N=256):
// MMA -> tanh*V epilogue -> exp -> per-tile sum(exp) + weighted column sum of values.

__global__ __launch_bounds__(512, 1)
void score_kernel(const float* __restrict__ values, const float* __restrict__ W1,
                  const float* __restrict__ Vw) {
    extern __shared__ char smem[];
    uint32_t* sA = (uint32_t*)(smem + SM_A);
    uint32_t* sB = (uint32_t*)(smem + SM_B);
    float* srow = (float*)(smem + SM_SROW);
    float* ses = (float*)(smem + SM_SES);
    float2* spart = (float2*)(smem + SM_SPART);

    const int tid = threadIdx.x;
    const int wid = tid >> 5, lane = tid & 31;
    const int mwarp = wid & 1, nwarp = wid >> 1;
    const int g = lane >> 2, tig = lane & 3;

    // Stage B once: W1[k][u] -> sB[u][kp] (half2 of k-pair).
#pragma unroll 4
    for (int i = tid; i < 256 * 128; i += 512) {
        int u = i & 255, kp = i >> 8;
        float x0 = __ldg(W1 + (size_t)(2 * kp) * Un + u);
        float x1 = __ldg(W1 + (size_t)(2 * kp + 1) * Un + u);
        sB[u * SAW + kp] = pack_half2(x0, x1);
    }

    float vw[8];
#pragma unroll
    for (int nt = 0; nt < 4; ++nt) {
        int c = nwarp * 32 + nt * 8 + 2 * tig;
        vw[2 * nt] = __ldg(Vw + c);
        vw[2 * nt + 1] = __ldg(Vw + c + 1);
    }

    const uint32_t sbA = smem_u32(sA), sbB = smem_u32(sB);
    const int t4 = lane >> 3, row_in = lane & 7;
    uint32_t adA[2];
#pragma unroll
    for (int mt = 0; mt < 2; ++mt) {
        int r = mwarp * 32 + mt * 16 + ((t4 & 1) << 3) + row_in;
        adA[mt] = sbA + (uint32_t)((r * SAW + ((t4 >> 1) << 2)) << 2);
    }
    uint32_t adB[2];
#pragma unroll
    for (int np = 0; np < 2; ++np) {
        int u = nwarp * 32 + np * 16 + ((t4 >> 1) << 3) + row_in;
        adB[np] = sbB + (uint32_t)((u * SAW + ((t4 & 1) << 2)) << 2);
    }

    // Prologue: stage A for first tile.
    {
        int tile = blockIdx.x;
        int b = tile >> 7, t0 = (tile & 127) * TM;
        const float2* v2 = (const float2*)(values + ((size_t)b * Tn + t0) * Dn);
#pragma unroll 4
        for (int i = tid; i < TM * 128; i += 512) {
            float2 x = v2[i];
            sA[(i >> 7) * SAW + (i & 127)] = pack_half2(x.x, x.y);
        }
    }
    __syncthreads();

    const int c2 = tid & 127, grp = tid >> 7;   // weighted-sum mapping

    int bufi = 0;
    for (int tile = blockIdx.x; tile < NTILES; tile += GRID_SCORE) {
        const int b = tile >> 7;
        const int t0 = (tile & 127) * TM;
        const int ntile = tile + GRID_SCORE;
        const int has_next = ntile < NTILES;

        // Prefetch next tile's values into registers (overlaps MMA).
        float2 pf[16];
        if (has_next) {
            const int nb = ntile >> 7, nt0 = (ntile & 127) * TM;
            const float2* v2 = (const float2*)(values + ((size_t)nb * Tn + nt0) * Dn);
#pragma unroll
            for (int j = 0; j < 16; ++j) pf[j] = __ldg(v2 + tid + j * 512);
        }

        float acc[2][4][4];
#pragma unroll
        for (int mt = 0; mt < 2; ++mt)
#pragma unroll
            for (int nt = 0; nt < 4; ++nt)
#pragma unroll
                for (int q = 0; q < 4; ++q) acc[mt][nt][q] = 0.f;

        const uint32_t abase = (uint32_t)(bufi * ABUF_BYTES);
#pragma unroll
        for (int ks = 0; ks < 16; ++ks) {
            const uint32_t ko = (uint32_t)ks * 32;
            uint32_t a0[4], a1[4], b0[4], b1[4];
            LDSM4(a0, adA[0] + abase + ko);
            LDSM4(a1, adA[1] + abase + ko);
            LDSM4(b0, adB[0] + ko);
            LDSM4(b1, adB[1] + ko);
            mma_fp16(acc[0][0], a0, b0[0], b0[1]);
            mma_fp16(acc[1][0], a1, b0[0], b0[1]);
            mma_fp16(acc[0][1], a0, b0[2], b0[3]);
            mma_fp16(acc[1][1], a1, b0[2], b0[3]);
            mma_fp16(acc[0][2], a0, b1[0], b1[1]);
            mma_fp16(acc[1][2], a1, b1[0], b1[1]);
            mma_fp16(acc[0][3], a0, b1[2], b1[3]);
            mma_fp16(acc[1][3], a1, b1[2], b1[3]);
        }

        // Store prefetched tile into other buffer (prev weighted-sum reads of it
        // were fenced by last iteration's syncthreads).
        if (has_next) {
            uint32_t* dst = (uint32_t*)(smem + SM_A + (bufi ^ 1) * ABUF_BYTES);
#pragma unroll
            for (int j = 0; j < 16; ++j) {
                int i = tid + j * 512;
                dst[(i >> 7) * SAW + (i & 127)] = pack_half2(pf[j].x, pf[j].y);
            }
        }

        // Epilogue: tanh(p + biasq) * Vw over this warp's 32 cols.
        const float* bq = g_biasq + b * Un;
        float rowsum[2][2] = {{0.f, 0.f}, {0.f, 0.f}};
#pragma unroll
        for (int nt = 0; nt < 4; ++nt) {
            int c = nwarp * 32 + nt * 8 + 2 * tig;
            float bq0 = __ldg(bq + c), bq1 = __ldg(bq + c + 1);
#pragma unroll
            for (int mt = 0; mt < 2; ++mt) {
                rowsum[mt][0] += tanh_fast(acc[mt][nt][0] + bq0) * vw[2 * nt]
                               + tanh_fast(acc[mt][nt][1] + bq1) * vw[2 * nt + 1];
                rowsum[mt][1] += tanh_fast(acc[mt][nt][2] + bq0) * vw[2 * nt]
                               + tanh_fast(acc[mt][nt][3] + bq1) * vw[2 * nt + 1];
            }
        }
#pragma unroll
        for (int mt = 0; mt < 2; ++mt)
#pragma unroll
            for (int j = 0; j < 2; ++j) {
                float v = rowsum[mt][j];
                v += __shfl_xor_sync(0xffffffffu, v, 1);
                v += __shfl_xor_sync(0xffffffffu, v, 2);
                rowsum[mt][j] = v;
            }
        if (tig == 0) {
#pragma unroll
            for (int mt = 0; mt < 2; ++mt) {
                int row = mwarp * 32 + mt * 16 + g;
                srow[row * 8 + nwarp] = rowsum[mt][0];
                srow[(row + 8) * 8 + nwarp] = rowsum[mt][1];
            }
        }
        __syncthreads();

        // Rows 0..63: final score, exp, per-tile Z partial.
        if (tid < TM) {
            const float4* s4 = (const float4*)(srow + tid * 8);
            float4 x = s4[0], y = s4[1];
            float s = ((x.x + x.y) + (x.z + x.w)) + ((y.x + y.y) + (y.z + y.w));
            float es = __expf(s);
            ses[tid] = es;
            g_escore[b * Tn + t0 + tid] = es;
            float zs = es;
#pragma unroll
            for (int o = 16; o; o >>= 1) zs += __shfl_xor_sync(0xffffffffu, zs, o);
            if (lane == 0) g_zp[tile * 2 + wid] = zs;
        }
        __syncthreads();

        // Weighted column sum: partial[d] = sum_t es[t] * v_fp16[t][d].
        {
            const uint32_t* sAv = (const uint32_t*)(smem + SM_A + bufi * ABUF_BYTES);
            float2 a2 = make_float2(0.f, 0.f);
#pragma unroll
            for (int j = 0; j < 16; ++j) {
                int t = grp * 16 + j;
                float es = ses[t];
                __half2 h = *(const __half2*)&sAv[t * SAW + c2];
                float2 v = __half22float2(h);
                a2.x += es * v.x;
                a2.y += es * v.y;
            }
            spart[grp * 128 + c2] = a2;
        }
        __syncthreads();
        if (grp == 0) {
            float2 p0 = spart[c2], p1 = spart[128 + c2];
            float2 p2 = spart[256 + c2], p3 = spart[384 + c2];
            float2 r;
            r.x = (p0.x + p1.x) + (p2.x + p3.x);
            r.y = (p0.y + p1.y) + (p2.y + p3.y);
            *(float2*)(g_partial + (size_t)tile * Dn + 2 * c2) = r;
        }
        __syncthreads();   // protects buf[bufi] (next STS target) + spart/srow/ses reuse
        bufi ^= 1;
    }
}

// ---------------- kernel 2: Z[b] = sum of per-tile exp sums ----------------

__global__ void stats_kernel() {
    int b = blockIdx.x, tid = threadIdx.x;
    __shared__ float red[8];
    float s = g_zp[b * 256 + tid];
#pragma unroll
    for (int o = 16; o; o >>= 1) s += __shfl_xor_sync(0xffffffffu, s, o);
    if ((tid & 31) == 0) red[tid >> 5] = s;
    __syncthreads();
    if (tid == 0) {
        float z = 0.f;
#pragma unroll
        for (int w = 0; w < 8; ++w) z += red[w];
        g_Z[b] = z;
    }
}

// ---------------- kernel 3: normalize weights ----------------

__global__ __launch_bounds__(256)
void norm_kernel(float* __restrict__ wout) {
    int b = blockIdx.y;
    int i = blockIdx.x * 1024 + threadIdx.x * 4;
    float invZ = 1.0f / g_Z[b];
    float4 e = *(const float4*)(g_escore + b * Tn + i);
    e.x *= invZ; e.y *= invZ; e.z *= invZ; e.w *= invZ;
    *(float4*)(wout + b * Tn + i) = e;
}

// ---------------- kernel 4: reduce context partials, scale by 1/Z ----------------

__global__ __launch_bounds__(64)
void reduce_kernel(float* __restrict__ ctx_out) {
    int b = blockIdx.y, d = blockIdx.x * 64 + threadIdx.x;
    float invZ = 1.0f / g_Z[b];
    const float* p = g_partial + (size_t)b * TPB * Dn + d;
    float s = 0.f;
#pragma unroll 8
    for (int c = 0; c < TPB; ++c) s += p[(size_t)c * Dn];
    ctx_out[b * Dn + d] = s * invZ;
}

// ---------------- launch ----------------

extern "C" void kernel_launch(void* const* d_in, const int* in_sizes, int n_in,
                              void* d_out, int out_size) {
    const float* values = (const float*)d_in[0];
    const float* query  = (const float*)d_in[1];
    const float* W1w    = (const float*)d_in[2];
    const float* W1b    = (const float*)d_in[3];
    const float* W2w    = (const float*)d_in[4];
    const float* W2b    = (const float*)d_in[5];
    const float* Vw     = (const float*)d_in[6];
    // d_in[7] = V_b: softmax-invariant constant, intentionally unused.
    (void)in_sizes; (void)n_in; (void)out_size;

    float* ctx_out = (float*)d_out;             // [B, D]
    float* w_out   = (float*)d_out + Bn * Dn;   // [B, T, 1]

    cudaFuncSetAttribute(score_kernel, cudaFuncAttributeMaxDynamicSharedMemorySize, SM_TOTAL);

    projq_kernel<<<Bn, 256>>>(query, W2w, W2b, W1b);
    score_kernel<<<GRID_SCORE, 512, SM_TOTAL>>>(values, W1w, Vw);
    stats_kernel<<<Bn, 256>>>();
    norm_kernel<<<dim3(Tn / 1024, Bn), 256>>>(w_out);
    reduce_kernel<<<dim3(4, Bn), 64>>>(ctx_out);
}

// round 7
// speedup vs baseline: 1.1106x; 1.1106x over previous
#include <cuda_runtime.h>
#include <cuda_fp16.h>
#include <cstdint>
#include <cstddef>

// BahdanauAttention B=16, T=8192, D=256, U=256 fp32.
// Baseline-PTX (ptxas sm_100): fp16 mma.sync + ldmatrix, persistent fused kernel:
// score GEMM + tanh(f16x2)*V epilogue + exp + per-tile context partials
// (values read exactly ONCE). Then a single finalize kernel (Z, weights, context).

#define Bn 16
#define Tn 8192
#define Dn 256
#define Un 256
#define TM 64                       // score tile M
#define TPB 128                     // tiles per batch
#define NTILES (Bn * TPB)           // 2048
#define GRID_SCORE 148

__device__ float g_escore[Bn * Tn];        // exp(score)
__device__ float g_biasq[Bn * Un];
__device__ float g_zp[NTILES * 2];         // per-tile partial sums of exp
__device__ float g_partial[NTILES * Dn];   // per-tile unnormalized context partials

// ---------------- helpers ----------------

__device__ __forceinline__ __half2 htanh2(__half2 x) {
    uint32_t xi = *(uint32_t*)&x, yo;
    asm("tanh.approx.f16x2 %0, %1;" : "=r"(yo) : "r"(xi));
    return *(__half2*)&yo;
}

__device__ __forceinline__ uint32_t pack_half2(float x, float y) {
    __half2 h = __floats2half2_rn(x, y);
    return *(uint32_t*)&h;
}

__device__ __forceinline__ uint32_t smem_u32(const void* p) {
    uint32_t a;
    asm("{ .reg .u64 t; cvta.to.shared.u64 t, %1; cvt.u32.u64 %0, t; }" : "=r"(a) : "l"(p));
    return a;
}

__device__ __forceinline__ void mma_fp16(float* c, const uint32_t* a, uint32_t b0, uint32_t b1) {
    asm volatile(
        "mma.sync.aligned.m16n8k16.row.col.f32.f16.f16.f32 "
        "{%0,%1,%2,%3},{%4,%5,%6,%7},{%8,%9},{%0,%1,%2,%3};"
        : "+f"(c[0]), "+f"(c[1]), "+f"(c[2]), "+f"(c[3])
        : "r"(a[0]), "r"(a[1]), "r"(a[2]), "r"(a[3]), "r"(b0), "r"(b1));
}

#define LDSM4(r, addr) \
    asm volatile("ldmatrix.sync.aligned.m8n8.x4.shared.b16 {%0,%1,%2,%3}, [%4];" \
                 : "=r"((r)[0]), "=r"((r)[1]), "=r"((r)[2]), "=r"((r)[3]) : "r"(addr))

// ---------------- smem layout (bytes) ----------------
#define SAW 132
#define ABUF_BYTES 33792                    // 64 rows x 132 words x 4B
#define SM_A 0
#define SM_B (2 * ABUF_BYTES)               // 67584
#define SM_SROW (SM_B + 135168)             // 202752
#define SM_SES (SM_SROW + 2048)             // 204800
#define SM_SPART (SM_SES + 256)             // 205056
#define SM_TOTAL (SM_SPART + 4096)          // 209152

// ---------------- kernel 0: biasq[b,u] = W1_b + W2_b + query@W2 ----------------

__global__ __launch_bounds__(256)
void projq_kernel(const float* __restrict__ query, const float* __restrict__ W2,
                  const float* __restrict__ W2b, const float* __restrict__ W1b) {
    int u = threadIdx.x, b = blockIdx.x;
    __shared__ float q[Dn];
    if (u < Dn) q[u] = query[b * Dn + u];
    __syncthreads();
    float acc[8] = {0.f, 0.f, 0.f, 0.f, 0.f, 0.f, 0.f, 0.f};
#pragma unroll 4
    for (int d0 = 0; d0 < Dn; d0 += 8) {
#pragma unroll
        for (int j = 0; j < 8; ++j)
            acc[j] += q[d0 + j] * __ldg(W2 + (size_t)(d0 + j) * Un + u);
    }
    float s = ((acc[0] + acc[1]) + (acc[2] + acc[3])) + ((acc[4] + acc[5]) + (acc[6] + acc[7]));
    g_biasq[b * Un + u] = s + W2b[u] + W1b[u];
}

// ---------------- kernel 1: persistent fused score+context kernel ----------------

__global__ __launch_bounds__(512, 1)
void score_kernel(const float* __restrict__ values, const float* __restrict__ W1,
                  const float* __restrict__ Vw) {
    extern __shared__ char smem[];
    uint32_t* sA = (uint32_t*)(smem + SM_A);
    uint32_t* sB = (uint32_t*)(smem + SM_B);
    float* srow = (float*)(smem + SM_SROW);
    float* ses = (float*)(smem + SM_SES);
    float2* spart = (float2*)(smem + SM_SPART);

    const int tid = threadIdx.x;
    const int wid = tid >> 5, lane = tid & 31;
    const int mwarp = wid & 1, nwarp = wid >> 1;
    const int g = lane >> 2, tig = lane & 3;

    // Stage B once: W1[k][u] -> sB[u][kp] (half2 of k-pair).
#pragma unroll 4
    for (int i = tid; i < 256 * 128; i += 512) {
        int u = i & 255, kp = i >> 8;
        float x0 = __ldg(W1 + (size_t)(2 * kp) * Un + u);
        float x1 = __ldg(W1 + (size_t)(2 * kp + 1) * Un + u);
        sB[u * SAW + kp] = pack_half2(x0, x1);
    }

    // Per-thread Vw pairs for cols c = nwarp*32 + nt*8 + 2tig + {0,1}.
    float2 vw2[4];
#pragma unroll
    for (int nt = 0; nt < 4; ++nt) {
        int c = nwarp * 32 + nt * 8 + 2 * tig;
        vw2[nt] = *(const float2*)(Vw + c);
    }

    const uint32_t sbA = smem_u32(sA), sbB = smem_u32(sB);
    const int t4 = lane >> 3, row_in = lane & 7;
    uint32_t adA[2];
#pragma unroll
    for (int mt = 0; mt < 2; ++mt) {
        int r = mwarp * 32 + mt * 16 + ((t4 & 1) << 3) + row_in;
        adA[mt] = sbA + (uint32_t)((r * SAW + ((t4 >> 1) << 2)) << 2);
    }
    uint32_t adB[2];
#pragma unroll
    for (int np = 0; np < 2; ++np) {
        int u = nwarp * 32 + np * 16 + ((t4 >> 1) << 3) + row_in;
        adB[np] = sbB + (uint32_t)((u * SAW + ((t4 & 1) << 2)) << 2);
    }

    // Prologue: stage A for first tile.
    {
        int tile = blockIdx.x;
        int b = tile >> 7, t0 = (tile & 127) * TM;
        const float2* v2 = (const float2*)(values + ((size_t)b * Tn + t0) * Dn);
#pragma unroll 4
        for (int i = tid; i < TM * 128; i += 512) {
            float2 x = v2[i];
            sA[(i >> 7) * SAW + (i & 127)] = pack_half2(x.x, x.y);
        }
    }
    __syncthreads();

    const int c2 = tid & 127, grp = tid >> 7;

    int bufi = 0;
    for (int tile = blockIdx.x; tile < NTILES; tile += GRID_SCORE) {
        const int b = tile >> 7;
        const int t0 = (tile & 127) * TM;
        const int ntile = tile + GRID_SCORE;
        const int has_next = ntile < NTILES;
        const float2* v2n = has_next
            ? (const float2*)(values + ((size_t)(ntile >> 7) * Tn + (ntile & 127) * TM) * Dn)
            : (const float2*)values;
        uint32_t* dst = (uint32_t*)(smem + SM_A + (bufi ^ 1) * ABUF_BYTES);

        float acc[2][4][4];
#pragma unroll
        for (int mt = 0; mt < 2; ++mt)
#pragma unroll
            for (int nt = 0; nt < 4; ++nt)
#pragma unroll
                for (int q = 0; q < 4; ++q) acc[mt][nt][q] = 0.f;

        // First half prefetch (8 float2 = 16 regs).
        float2 pf[8];
        if (has_next) {
#pragma unroll
            for (int j = 0; j < 8; ++j) pf[j] = __ldg(v2n + tid + j * 512);
        }

        const uint32_t abase = (uint32_t)(bufi * ABUF_BYTES);
#pragma unroll
        for (int ks = 0; ks < 8; ++ks) {
            const uint32_t ko = (uint32_t)ks * 32;
            uint32_t a0[4], a1[4], b0[4], b1[4];
            LDSM4(a0, adA[0] + abase + ko);
            LDSM4(a1, adA[1] + abase + ko);
            LDSM4(b0, adB[0] + ko);
            LDSM4(b1, adB[1] + ko);
            mma_fp16(acc[0][0], a0, b0[0], b0[1]);
            mma_fp16(acc[1][0], a1, b0[0], b0[1]);
            mma_fp16(acc[0][1], a0, b0[2], b0[3]);
            mma_fp16(acc[1][1], a1, b0[2], b0[3]);
            mma_fp16(acc[0][2], a0, b1[0], b1[1]);
            mma_fp16(acc[1][2], a1, b1[0], b1[1]);
            mma_fp16(acc[0][3], a0, b1[2], b1[3]);
            mma_fp16(acc[1][3], a1, b1[2], b1[3]);
        }

        // Store first half, prefetch second half (reuse pf regs).
        if (has_next) {
#pragma unroll
            for (int j = 0; j < 8; ++j) {
                int i = tid + j * 512;
                dst[(i >> 7) * SAW + (i & 127)] = pack_half2(pf[j].x, pf[j].y);
            }
#pragma unroll
            for (int j = 0; j < 8; ++j) pf[j] = __ldg(v2n + tid + (8 + j) * 512);
        }

#pragma unroll
        for (int ks = 8; ks < 16; ++ks) {
            const uint32_t ko = (uint32_t)ks * 32;
            uint32_t a0[4], a1[4], b0[4], b1[4];
            LDSM4(a0, adA[0] + abase + ko);
            LDSM4(a1, adA[1] + abase + ko);
            LDSM4(b0, adB[0] + ko);
            LDSM4(b1, adB[1] + ko);
            mma_fp16(acc[0][0], a0, b0[0], b0[1]);
            mma_fp16(acc[1][0], a1, b0[0], b0[1]);
            mma_fp16(acc[0][1], a0, b0[2], b0[3]);
            mma_fp16(acc[1][1], a1, b0[2], b0[3]);
            mma_fp16(acc[0][2], a0, b1[0], b1[1]);
            mma_fp16(acc[1][2], a1, b1[0], b1[1]);
            mma_fp16(acc[0][3], a0, b1[2], b1[3]);
            mma_fp16(acc[1][3], a1, b1[2], b1[3]);
        }

        if (has_next) {
#pragma unroll
            for (int j = 0; j < 8; ++j) {
                int i = tid + (8 + j) * 512;
                dst[(i >> 7) * SAW + (i & 127)] = pack_half2(pf[j].x, pf[j].y);
            }
        }

        // Epilogue: tanh(f16x2) of fp32-biased sums, fp32 product accumulation.
        const float* bq = g_biasq + b * Un;
        float rowsum[2][2] = {{0.f, 0.f}, {0.f, 0.f}};
#pragma unroll
        for (int nt = 0; nt < 4; ++nt) {
            int c = nwarp * 32 + nt * 8 + 2 * tig;
            float2 bq2 = *(const float2*)(bq + c);
#pragma unroll
            for (int mt = 0; mt < 2; ++mt) {
                __half2 x01 = __floats2half2_rn(acc[mt][nt][0] + bq2.x, acc[mt][nt][1] + bq2.y);
                float2 f01 = __half22float2(htanh2(x01));
                rowsum[mt][0] += f01.x * vw2[nt].x + f01.y * vw2[nt].y;
                __half2 x23 = __floats2half2_rn(acc[mt][nt][2] + bq2.x, acc[mt][nt][3] + bq2.y);
                float2 f23 = __half22float2(htanh2(x23));
                rowsum[mt][1] += f23.x * vw2[nt].x + f23.y * vw2[nt].y;
            }
        }
#pragma unroll
        for (int mt = 0; mt < 2; ++mt)
#pragma unroll
            for (int j = 0; j < 2; ++j) {
                float v = rowsum[mt][j];
                v += __shfl_xor_sync(0xffffffffu, v, 1);
                v += __shfl_xor_sync(0xffffffffu, v, 2);
                rowsum[mt][j] = v;
            }
        if (tig == 0) {
#pragma unroll
            for (int mt = 0; mt < 2; ++mt) {
                int row = mwarp * 32 + mt * 16 + g;
                srow[row * 8 + nwarp] = rowsum[mt][0];
                srow[(row + 8) * 8 + nwarp] = rowsum[mt][1];
            }
        }
        __syncthreads();

        if (tid < TM) {
            const float4* s4 = (const float4*)(srow + tid * 8);
            float4 x = s4[0], y = s4[1];
            float s = ((x.x + x.y) + (x.z + x.w)) + ((y.x + y.y) + (y.z + y.w));
            float es = __expf(s);
            ses[tid] = es;
            g_escore[b * Tn + t0 + tid] = es;
            float zs = es;
#pragma unroll
            for (int o = 16; o; o >>= 1) zs += __shfl_xor_sync(0xffffffffu, zs, o);
            if (lane == 0) g_zp[tile * 2 + wid] = zs;
        }
        __syncthreads();

        // Weighted column sum from the fp16 tile: partial[d] = sum_t es[t]*v[t][d].
        {
            const uint32_t* sAv = (const uint32_t*)(smem + SM_A + bufi * ABUF_BYTES);
            float2 a2 = make_float2(0.f, 0.f);
#pragma unroll
            for (int j = 0; j < 16; ++j) {
                int t = grp * 16 + j;
                float es = ses[t];
                __half2 h = *(const __half2*)&sAv[t * SAW + c2];
                float2 v = __half22float2(h);
                a2.x += es * v.x;
                a2.y += es * v.y;
            }
            spart[grp * 128 + c2] = a2;
        }
        __syncthreads();
        if (grp == 0) {
            float2 p0 = spart[c2], p1 = spart[128 + c2];
            float2 p2 = spart[256 + c2], p3 = spart[384 + c2];
            float2 r;
            r.x = (p0.x + p1.x) + (p2.x + p3.x);
            r.y = (p0.y + p1.y) + (p2.y + p3.y);
            *(float2*)(g_partial + (size_t)tile * Dn + 2 * c2) = r;
        }
        __syncthreads();
        bufi ^= 1;
    }
}

// ---------------- kernel 2: finalize (Z, weight normalize, context) ----------------

__global__ __launch_bounds__(512)
void finalize_kernel(float* __restrict__ ctx_out, float* __restrict__ w_out) {
    int b = blockIdx.x, tid = threadIdx.x;
    int wid = tid >> 5, lane = tid & 31;
    __shared__ float red[16];
    __shared__ float zsh;
    __shared__ float cpart[512];

    // Z[b] = sum of 256 per-tile partials.
    float s = (tid < 256) ? g_zp[b * 256 + tid] : 0.f;
#pragma unroll
    for (int o = 16; o; o >>= 1) s += __shfl_xor_sync(0xffffffffu, s, o);
    if (lane == 0) red[wid] = s;
    __syncthreads();
    if (tid == 0) {
        float z = 0.f;
#pragma unroll
        for (int w = 0; w < 16; ++w) z += red[w];
        zsh = z;
    }
    __syncthreads();
    float invZ = 1.0f / zsh;

    // Normalize weights: 8192 per batch, 4 float4 per thread.
    const float4* es4 = (const float4*)(g_escore + (size_t)b * Tn);
    float4* w4 = (float4*)(w_out + (size_t)b * Tn);
#pragma unroll
    for (int j = 0; j < 4; ++j) {
        float4 v = es4[tid + j * 512];
        v.x *= invZ; v.y *= invZ; v.z *= invZ; v.w *= invZ;
        w4[tid + j * 512] = v;
    }

    // Context: reduce 128 per-tile partials over d.
    int half = tid >> 8, d = tid & 255;
    const float* p = g_partial + ((size_t)b * TPB + half * 64) * Dn + d;
    float a = 0.f;
#pragma unroll 8
    for (int c = 0; c < 64; ++c) a += p[(size_t)c * Dn];
    cpart[tid] = a;
    __syncthreads();
    if (tid < 256) ctx_out[b * Dn + tid] = (cpart[tid] + cpart[tid + 256]) * invZ;
}

// ---------------- launch ----------------

extern "C" void kernel_launch(void* const* d_in, const int* in_sizes, int n_in,
                              void* d_out, int out_size) {
    const float* values = (const float*)d_in[0];
    const float* query  = (const float*)d_in[1];
    const float* W1w    = (const float*)d_in[2];
    const float* W1b    = (const float*)d_in[3];
    const float* W2w    = (const float*)d_in[4];
    const float* W2b    = (const float*)d_in[5];
    const float* Vw     = (const float*)d_in[6];
    // d_in[7] = V_b: softmax-invariant constant, intentionally unused.
    (void)in_sizes; (void)n_in; (void)out_size;

    float* ctx_out = (float*)d_out;             // [B, D]
    float* w_out   = (float*)d_out + Bn * Dn;   // [B, T, 1]

    cudaFuncSetAttribute(score_kernel, cudaFuncAttributeMaxDynamicSharedMemorySize, SM_TOTAL);

    projq_kernel<<<Bn, 256>>>(query, W2w, W2b, W1b);
    score_kernel<<<GRID_SCORE, 512, SM_TOTAL>>>(values, W1w, Vw);
    finalize_kernel<<<Bn, 512>>>(ctx_out, w_out);
}

// round 8
// speedup vs baseline: 1.2532x; 1.1284x over previous
#include <cuda_runtime.h>
#include <cuda_fp16.h>
#include <cstdint>
#include <cstddef>

// BahdanauAttention B=16, T=8192, D=256, U=256 fp32.
// Baseline-PTX (ptxas sm_100): fp16 mma.sync + ldmatrix, persistent fused kernel:
// score GEMM + tanh(f16x2)*V epilogue + exp + per-tile context partials
// (values read exactly ONCE). Wide-parallel projq; single finalize kernel.

#define Bn 16
#define Tn 8192
#define Dn 256
#define Un 256
#define TM 64                       // score tile M
#define TPB 128                     // tiles per batch
#define NTILES (Bn * TPB)           // 2048
#define GRID_SCORE 148

__device__ float g_escore[Bn * Tn];        // exp(score)
__device__ float g_biasq[Bn * Un];
__device__ float g_zp[NTILES * 2];         // per-tile partial sums of exp
__device__ float g_partial[NTILES * Dn];   // per-tile unnormalized context partials

// ---------------- helpers ----------------

__device__ __forceinline__ __half2 htanh2(__half2 x) {
    uint32_t xi = *(uint32_t*)&x, yo;
    asm("tanh.approx.f16x2 %0, %1;" : "=r"(yo) : "r"(xi));
    return *(__half2*)&yo;
}

__device__ __forceinline__ uint32_t pack_half2(float x, float y) {
    __half2 h = __floats2half2_rn(x, y);
    return *(uint32_t*)&h;
}

__device__ __forceinline__ uint32_t smem_u32(const void* p) {
    uint32_t a;
    asm("{ .reg .u64 t; cvta.to.shared.u64 t, %1; cvt.u32.u64 %0, t; }" : "=r"(a) : "l"(p));
    return a;
}

__device__ __forceinline__ void mma_fp16(float* c, const uint32_t* a, uint32_t b0, uint32_t b1) {
    asm volatile(
        "mma.sync.aligned.m16n8k16.row.col.f32.f16.f16.f32 "
        "{%0,%1,%2,%3},{%4,%5,%6,%7},{%8,%9},{%0,%1,%2,%3};"
        : "+f"(c[0]), "+f"(c[1]), "+f"(c[2]), "+f"(c[3])
        : "r"(a[0]), "r"(a[1]), "r"(a[2]), "r"(a[3]), "r"(b0), "r"(b1));
}

#define LDSM4(r, addr) \
    asm volatile("ldmatrix.sync.aligned.m8n8.x4.shared.b16 {%0,%1,%2,%3}, [%4];" \
                 : "=r"((r)[0]), "=r"((r)[1]), "=r"((r)[2]), "=r"((r)[3]) : "r"(addr))

// ---------------- smem layout (bytes) ----------------
#define SAW 132
#define ABUF_BYTES 33792                    // 64 rows x 132 words x 4B
#define SM_A 0
#define SM_B (2 * ABUF_BYTES)               // 67584
#define SM_SROW (SM_B + 135168)             // 202752
#define SM_SES (SM_SROW + 2048)             // 204800
#define SM_SPART (SM_SES + 256)             // 205056
#define SM_TOTAL (SM_SPART + 4096)          // 209152

// ---------------- kernel 0: biasq[b,u] = W1_b + W2_b + query@W2 ----------------
// Grid (16 u-chunks, 16 batches) x 256 threads. Thread (u = tid&15 within chunk,
// dpart = tid>>4): 16-deep partial; smem reduce over 16 dparts.

__global__ __launch_bounds__(256)
void projq_kernel(const float* __restrict__ query, const float* __restrict__ W2,
                  const float* __restrict__ W2b, const float* __restrict__ W1b) {
    const int b = blockIdx.y;
    const int u0 = blockIdx.x * 16;
    const int tid = threadIdx.x;
    const int ul = tid & 15, dpart = tid >> 4;

    __shared__ float q[Dn];
    __shared__ float part[16][17];

    if (tid < Dn) q[tid] = query[b * Dn + tid];
    __syncthreads();

    const int u = u0 + ul;
    float acc = 0.f;
#pragma unroll
    for (int i = 0; i < 16; ++i) {
        int d = dpart * 16 + i;
        acc += q[d] * __ldg(W2 + (size_t)d * Un + u);
    }
    part[dpart][ul] = acc;
    __syncthreads();

    if (tid < 16) {
        float s = 0.f;
#pragma unroll
        for (int p = 0; p < 16; ++p) s += part[p][tid];
        int uu = u0 + tid;
        g_biasq[b * Un + uu] = s + W2b[uu] + W1b[uu];
    }
}

// ---------------- kernel 1: persistent fused score+context kernel ----------------

__global__ __launch_bounds__(512, 1)
void score_kernel(const float* __restrict__ values, const float* __restrict__ W1,
                  const float* __restrict__ Vw) {
    extern __shared__ char smem[];
    uint32_t* sA = (uint32_t*)(smem + SM_A);
    uint32_t* sB = (uint32_t*)(smem + SM_B);
    float* srow = (float*)(smem + SM_SROW);
    float* ses = (float*)(smem + SM_SES);
    float2* spart = (float2*)(smem + SM_SPART);

    const int tid = threadIdx.x;
    const int wid = tid >> 5, lane = tid & 31;
    const int mwarp = wid & 1, nwarp = wid >> 1;
    const int g = lane >> 2, tig = lane & 3;

    // Stage B once: W1[k][u] -> sB[u][kp] (half2 of k-pair).
#pragma unroll 4
    for (int i = tid; i < 256 * 128; i += 512) {
        int u = i & 255, kp = i >> 8;
        float x0 = __ldg(W1 + (size_t)(2 * kp) * Un + u);
        float x1 = __ldg(W1 + (size_t)(2 * kp + 1) * Un + u);
        sB[u * SAW + kp] = pack_half2(x0, x1);
    }

    // Per-thread Vw pairs for cols c = nwarp*32 + nt*8 + 2tig + {0,1}.
    float2 vw2[4];
#pragma unroll
    for (int nt = 0; nt < 4; ++nt) {
        int c = nwarp * 32 + nt * 8 + 2 * tig;
        vw2[nt] = *(const float2*)(Vw + c);
    }

    const uint32_t sbA = smem_u32(sA), sbB = smem_u32(sB);
    const int t4 = lane >> 3, row_in = lane & 7;
    uint32_t adA[2];
#pragma unroll
    for (int mt = 0; mt < 2; ++mt) {
        int r = mwarp * 32 + mt * 16 + ((t4 & 1) << 3) + row_in;
        adA[mt] = sbA + (uint32_t)((r * SAW + ((t4 >> 1) << 2)) << 2);
    }
    uint32_t adB[2];
#pragma unroll
    for (int np = 0; np < 2; ++np) {
        int u = nwarp * 32 + np * 16 + ((t4 >> 1) << 3) + row_in;
        adB[np] = sbB + (uint32_t)((u * SAW + ((t4 & 1) << 2)) << 2);
    }

    // Prologue: stage A for first tile.
    {
        int tile = blockIdx.x;
        int b = tile >> 7, t0 = (tile & 127) * TM;
        const float2* v2 = (const float2*)(values + ((size_t)b * Tn + t0) * Dn);
#pragma unroll 4
        for (int i = tid; i < TM * 128; i += 512) {
            float2 x = v2[i];
            sA[(i >> 7) * SAW + (i & 127)] = pack_half2(x.x, x.y);
        }
    }
    __syncthreads();

    const int c2 = tid & 127, grp = tid >> 7;

    int bufi = 0;
    for (int tile = blockIdx.x; tile < NTILES; tile += GRID_SCORE) {
        const int b = tile >> 7;
        const int t0 = (tile & 127) * TM;
        const int ntile = tile + GRID_SCORE;
        const int has_next = ntile < NTILES;
        const float2* v2n = has_next
            ? (const float2*)(values + ((size_t)(ntile >> 7) * Tn + (ntile & 127) * TM) * Dn)
            : (const float2*)values;
        uint32_t* dst = (uint32_t*)(smem + SM_A + (bufi ^ 1) * ABUF_BYTES);

        float acc[2][4][4];
#pragma unroll
        for (int mt = 0; mt < 2; ++mt)
#pragma unroll
            for (int nt = 0; nt < 4; ++nt)
#pragma unroll
                for (int q = 0; q < 4; ++q) acc[mt][nt][q] = 0.f;

        // First half prefetch (8 float2 = 16 regs).
        float2 pf[8];
        if (has_next) {
#pragma unroll
            for (int j = 0; j < 8; ++j) pf[j] = __ldg(v2n + tid + j * 512);
        }

        const uint32_t abase = (uint32_t)(bufi * ABUF_BYTES);
#pragma unroll
        for (int ks = 0; ks < 8; ++ks) {
            const uint32_t ko = (uint32_t)ks * 32;
            uint32_t a0[4], a1[4], b0[4], b1[4];
            LDSM4(a0, adA[0] + abase + ko);
            LDSM4(a1, adA[1] + abase + ko);
            LDSM4(b0, adB[0] + ko);
            LDSM4(b1, adB[1] + ko);
            mma_fp16(acc[0][0], a0, b0[0], b0[1]);
            mma_fp16(acc[1][0], a1, b0[0], b0[1]);
            mma_fp16(acc[0][1], a0, b0[2], b0[3]);
            mma_fp16(acc[1][1], a1, b0[2], b0[3]);
            mma_fp16(acc[0][2], a0, b1[0], b1[1]);
            mma_fp16(acc[1][2], a1, b1[0], b1[1]);
            mma_fp16(acc[0][3], a0, b1[2], b1[3]);
            mma_fp16(acc[1][3], a1, b1[2], b1[3]);
        }

        // Store first half, prefetch second half (reuse pf regs).
        if (has_next) {
#pragma unroll
            for (int j = 0; j < 8; ++j) {
                int i = tid + j * 512;
                dst[(i >> 7) * SAW + (i & 127)] = pack_half2(pf[j].x, pf[j].y);
            }
#pragma unroll
            for (int j = 0; j < 8; ++j) pf[j] = __ldg(v2n + tid + (8 + j) * 512);
        }

#pragma unroll
        for (int ks = 8; ks < 16; ++ks) {
            const uint32_t ko = (uint32_t)ks * 32;
            uint32_t a0[4], a1[4], b0[4], b1[4];
            LDSM4(a0, adA[0] + abase + ko);
            LDSM4(a1, adA[1] + abase + ko);
            LDSM4(b0, adB[0] + ko);
            LDSM4(b1, adB[1] + ko);
            mma_fp16(acc[0][0], a0, b0[0], b0[1]);
            mma_fp16(acc[1][0], a1, b0[0], b0[1]);
            mma_fp16(acc[0][1], a0, b0[2], b0[3]);
            mma_fp16(acc[1][1], a1, b0[2], b0[3]);
            mma_fp16(acc[0][2], a0, b1[0], b1[1]);
            mma_fp16(acc[1][2], a1, b1[0], b1[1]);
            mma_fp16(acc[0][3], a0, b1[2], b1[3]);
            mma_fp16(acc[1][3], a1, b1[2], b1[3]);
        }

        if (has_next) {
#pragma unroll
            for (int j = 0; j < 8; ++j) {
                int i = tid + (8 + j) * 512;
                dst[(i >> 7) * SAW + (i & 127)] = pack_half2(pf[j].x, pf[j].y);
            }
        }

        // Epilogue: tanh(f16x2) of fp32-biased sums, fp32 product accumulation.
        const float* bq = g_biasq + b * Un;
        float rowsum[2][2] = {{0.f, 0.f}, {0.f, 0.f}};
#pragma unroll
        for (int nt = 0; nt < 4; ++nt) {
            int c = nwarp * 32 + nt * 8 + 2 * tig;
            float2 bq2 = *(const float2*)(bq + c);
#pragma unroll
            for (int mt = 0; mt < 2; ++mt) {
                __half2 x01 = __floats2half2_rn(acc[mt][nt][0] + bq2.x, acc[mt][nt][1] + bq2.y);
                float2 f01 = __half22float2(htanh2(x01));
                rowsum[mt][0] += f01.x * vw2[nt].x + f01.y * vw2[nt].y;
                __half2 x23 = __floats2half2_rn(acc[mt][nt][2] + bq2.x, acc[mt][nt][3] + bq2.y);
                float2 f23 = __half22float2(htanh2(x23));
                rowsum[mt][1] += f23.x * vw2[nt].x + f23.y * vw2[nt].y;
            }
        }
#pragma unroll
        for (int mt = 0; mt < 2; ++mt)
#pragma unroll
            for (int j = 0; j < 2; ++j) {
                float v = rowsum[mt][j];
                v += __shfl_xor_sync(0xffffffffu, v, 1);
                v += __shfl_xor_sync(0xffffffffu, v, 2);
                rowsum[mt][j] = v;
            }
        if (tig == 0) {
#pragma unroll
            for (int mt = 0; mt < 2; ++mt) {
                int row = mwarp * 32 + mt * 16 + g;
                srow[row * 8 + nwarp] = rowsum[mt][0];
                srow[(row + 8) * 8 + nwarp] = rowsum[mt][1];
            }
        }
        __syncthreads();

        if (tid < TM) {
            const float4* s4 = (const float4*)(srow + tid * 8);
            float4 x = s4[0], y = s4[1];
            float s = ((x.x + x.y) + (x.z + x.w)) + ((y.x + y.y) + (y.z + y.w));
            float es = __expf(s);
            ses[tid] = es;
            g_escore[b * Tn + t0 + tid] = es;
            float zs = es;
#pragma unroll
            for (int o = 16; o; o >>= 1) zs += __shfl_xor_sync(0xffffffffu, zs, o);
            if (lane == 0) g_zp[tile * 2 + wid] = zs;
        }
        __syncthreads();

        // Weighted column sum from the fp16 tile: partial[d] = sum_t es[t]*v[t][d].
        {
            const uint32_t* sAv = (const uint32_t*)(smem + SM_A + bufi * ABUF_BYTES);
            float2 a2 = make_float2(0.f, 0.f);
#pragma unroll
            for (int j = 0; j < 16; ++j) {
                int t = grp * 16 + j;
                float es = ses[t];
                __half2 h = *(const __half2*)&sAv[t * SAW + c2];
                float2 v = __half22float2(h);
                a2.x += es * v.x;
                a2.y += es * v.y;
            }
            spart[grp * 128 + c2] = a2;
        }
        __syncthreads();
        if (grp == 0) {
            float2 p0 = spart[c2], p1 = spart[128 + c2];
            float2 p2 = spart[256 + c2], p3 = spart[384 + c2];
            float2 r;
            r.x = (p0.x + p1.x) + (p2.x + p3.x);
            r.y = (p0.y + p1.y) + (p2.y + p3.y);
            *(float2*)(g_partial + (size_t)tile * Dn + 2 * c2) = r;
        }
        // NOTE: no sync needed here. grp0's spart reads precede the next tile's
        // spart writes (separated by next tile's srow sync); this tile's sA[bufi]
        // weighted-sum reads precede next tile's STS to the same buffer (separated
        // by the spart sync above).
        bufi ^= 1;
    }
}

// ---------------- kernel 2: finalize (Z, weight normalize, context) ----------------

__global__ __launch_bounds__(512)
void finalize_kernel(float* __restrict__ ctx_out, float* __restrict__ w_out) {
    int b = blockIdx.x, tid = threadIdx.x;
    int wid = tid >> 5, lane = tid & 31;
    __shared__ float red[16];
    __shared__ float zsh;
    __shared__ float cpart[512];

    // Z[b] = sum of 256 per-tile partials.
    float s = (tid < 256) ? g_zp[b * 256 + tid] : 0.f;
#pragma unroll
    for (int o = 16; o; o >>= 1) s += __shfl_xor_sync(0xffffffffu, s, o);
    if (lane == 0) red[wid] = s;
    __syncthreads();
    if (tid == 0) {
        float z = 0.f;
#pragma unroll
        for (int w = 0; w < 16; ++w) z += red[w];
        zsh = z;
    }
    __syncthreads();
    float invZ = 1.0f / zsh;

    // Normalize weights: 8192 per batch, 4 float4 per thread.
    const float4* es4 = (const float4*)(g_escore + (size_t)b * Tn);
    float4* w4 = (float4*)(w_out + (size_t)b * Tn);
#pragma unroll
    for (int j = 0; j < 4; ++j) {
        float4 v = es4[tid + j * 512];
        v.x *= invZ; v.y *= invZ; v.z *= invZ; v.w *= invZ;
        w4[tid + j * 512] = v;
    }

    // Context: reduce 128 per-tile partials over d.
    int half = tid >> 8, d = tid & 255;
    const float* p = g_partial + ((size_t)b * TPB + half * 64) * Dn + d;
    float a = 0.f;
#pragma unroll 8
    for (int c = 0; c < 64; ++c) a += p[(size_t)c * Dn];
    cpart[tid] = a;
    __syncthreads();
    if (tid < 256) ctx_out[b * Dn + tid] = (cpart[tid] + cpart[tid + 256]) * invZ;
}

// ---------------- launch ----------------

extern "C" void kernel_launch(void* const* d_in, const int* in_sizes, int n_in,
                              void* d_out, int out_size) {
    const float* values = (const float*)d_in[0];
    const float* query  = (const float*)d_in[1];
    const float* W1w    = (const float*)d_in[2];
    const float* W1b    = (const float*)d_in[3];
    const float* W2w    = (const float*)d_in[4];
    const float* W2b    = (const float*)d_in[5];
    const float* Vw     = (const float*)d_in[6];
    // d_in[7] = V_b: softmax-invariant constant, intentionally unused.
    (void)in_sizes; (void)n_in; (void)out_size;

    float* ctx_out = (float*)d_out;             // [B, D]
    float* w_out   = (float*)d_out + Bn * Dn;   // [B, T, 1]

    cudaFuncSetAttribute(score_kernel, cudaFuncAttributeMaxDynamicSharedMemorySize, SM_TOTAL);

    projq_kernel<<<dim3(16, Bn), 256>>>(query, W2w, W2b, W1b);
    score_kernel<<<GRID_SCORE, 512, SM_TOTAL>>>(values, W1w, Vw);
    finalize_kernel<<<Bn, 512>>>(ctx_out, w_out);
}